// round 11
// baseline (speedup 1.0000x reference)
#include <cuda_runtime.h>
#include <cstddef>
#include <cstdint>

#define DIM 512
#define HID 2048
#define NBR 512
#define ND (NBR*DIM)
#define NSTEPS 8
#define SUBSTEPS 2

// ---------------- device scratch (static allocation, allowed) ----------------
__device__ float g_y[DIM];
__device__ float g_Dy[ND];
__device__ float g_a[4*HID];                  // one slot per RK4 stage (WAR-free)
__device__ float g_kdy[4*DIM];
__device__ float g_kDy[4*ND];                 // reduced kDy per stage (s=3 unused)
__device__ float g_kDyP[8*ND];                // GEMM-C split-K partials (z=8)
__device__ float g_G[2*(size_t)NBR*HID];      // GEMM-G split-K partials (z=2), raw
__device__ float g_W1Th[(size_t)HID*DIM], g_W1Tl[(size_t)HID*DIM];  // W1^T split [2048x512]
__device__ float g_W2Th[(size_t)DIM*HID], g_W2Tl[(size_t)DIM*HID];  // W2^T split [512x2048]
__device__ float g_W1T[(size_t)HID*DIM];      // W1^T full fp32 (for matvec)
__device__ float g_W2T[(size_t)DIM*HID];      // W2^T full fp32 (for matvec)

// ---------------- PTX helpers (all sm_80 family-common; NO tcgen05) ----------------
static __device__ __forceinline__ uint32_t s2u(const void* p) {
    uint32_t a;
    asm("{ .reg .u64 t; cvta.to.shared.u64 t, %1; cvt.u32.u64 %0, t; }" : "=r"(a) : "l"(p));
    return a;
}
static __device__ __forceinline__ void cp16(uint32_t s, const void* g) {
    asm volatile("cp.async.cg.shared.global [%0], [%1], 16;" :: "r"(s), "l"(g));
}
static __device__ __forceinline__ uint32_t swz(uint32_t o) { return o ^ ((o >> 3) & 0x70); }

static __device__ __forceinline__ void ldsm4(uint32_t* r, uint32_t addr) {
    asm volatile("ldmatrix.sync.aligned.m8n8.x4.shared.b16 {%0,%1,%2,%3}, [%4];"
                 : "=r"(r[0]), "=r"(r[1]), "=r"(r[2]), "=r"(r[3]) : "r"(addr));
}
static __device__ __forceinline__ void mma8(float* c, const uint32_t* a, const uint32_t* b) {
    asm volatile("mma.sync.aligned.m16n8k8.row.col.f32.tf32.tf32.f32 "
                 "{%0,%1,%2,%3}, {%4,%5,%6,%7}, {%8,%9}, {%0,%1,%2,%3};"
                 : "+f"(c[0]), "+f"(c[1]), "+f"(c[2]), "+f"(c[3])
                 : "r"(a[0]), "r"(a[1]), "r"(a[2]), "r"(a[3]), "r"(b[0]), "r"(b[1]));
}

// tf32 hi/lo split: x ≈ h + l, both tf32-representable; product error ~2^-21
static __device__ __forceinline__ void tf32split(float x, float& h, float& l) {
    uint32_t hb; asm("cvt.rna.tf32.f32 %0, %1;" : "=r"(hb) : "f"(x));
    float hf = __uint_as_float(hb);
    float r = x - hf;
    uint32_t lb; asm("cvt.rna.tf32.f32 %0, %1;" : "=r"(lb) : "f"(r));
    h = hf; l = __uint_as_float(lb);
}

// ---------------- mma.sync tf32 GEMM with FUSED A-prep, 3-pass split ----------------
// AMODE 1: x = A + c*A2 (A2 may be null)            [GEMM-G: RK4 stage axpy]
// AMODE 2: u = A + A2; x = s*u*(1-a*u), a=avec[k]   [GEMM-C: G-sum + tanh-Jacobian epi]
#define KCH 32
#define NCH 8
#define KSUB 256
#define TILE_B (128*KCH*4)
#define BUF_B (4*TILE_B)
#define GEMM_SMEM (2*BUF_B)

template<int AMODE>
__global__ void __launch_bounds__(256, 1)
gemm_mma(const float* __restrict__ A, const float* __restrict__ A2, int lda,
         const float* __restrict__ ts, int interval, float cmul,
         const float* __restrict__ avec,
         const float* __restrict__ Bh, const float* __restrict__ Bl, int ldb,
         float* __restrict__ Cbase, int ldc, size_t zstride)
{
    extern __shared__ __align__(1024) char smem[];
    const uint32_t sb = s2u(smem);
    const int t = threadIdx.x, lane = t & 31, wid = t >> 5;
    const int nb = blockIdx.x, mb = blockIdx.y, z = blockIdx.z;
    const int kbase = z * KSUB;
    const int m0w = (wid & 1) * 64, n0w = (wid >> 1) * 32;

    float c = 0.f;
    if (AMODE == 1)
        c = cmul * (ts[interval+1] - ts[interval]) * (1.0f / SUBSTEPS);

    const int rAl = (lane & 7) + ((lane >> 3) & 1) * 8;
    const int hA  = (lane >> 4) * 16;
    const int rBl = (lane & 7) + ((lane >> 4) & 1) * 8;
    const int hB  = ((lane >> 3) & 1) * 16;
    uint32_t rowA[4], crA[4], rowB[2], crB[2];
    #pragma unroll
    for (int i = 0; i < 4; i++) {
        int row = m0w + i * 16 + rAl;
        rowA[i] = (uint32_t)row * 128u; crA[i] = (uint32_t)(row & 7) * 16u;
    }
    #pragma unroll
    for (int jp = 0; jp < 2; jp++) {
        int row = n0w + jp * 16 + rBl;
        rowB[jp] = (uint32_t)row * 128u; crB[jp] = (uint32_t)(row & 7) * 16u;
    }

    float acc[4][4][4];
    #pragma unroll
    for (int i = 0; i < 4; i++)
        #pragma unroll
        for (int j = 0; j < 4; j++)
            #pragma unroll
            for (int q = 0; q < 4; q++) acc[i][j][q] = 0.f;

    const int ar = t >> 3, ac = t & 7;
    float4 pa[4], pb[4], va;

    auto ldg_A = [&](int ch) {
        int k0 = kbase + ch * KCH + ac * 4;
        #pragma unroll
        for (int i = 0; i < 4; i++) {
            size_t off = (size_t)(mb * 128 + i * 32 + ar) * lda + k0;
            pa[i] = *(const float4*)(A + off);
            if (AMODE == 2)        pb[i] = *(const float4*)(A2 + off);
            else if (A2)           pb[i] = *(const float4*)(A2 + off);
        }
        if (AMODE == 2) va = *(const float4*)(avec + k0);
    };
    auto sts_A = [&](int buf) {
        #pragma unroll
        for (int i = 0; i < 4; i++) {
            float4 x = pa[i];
            if (AMODE == 1) {
                if (A2) { x.x += c*pb[i].x; x.y += c*pb[i].y; x.z += c*pb[i].z; x.w += c*pb[i].w; }
            } else {
                float4 u = make_float4(x.x+pb[i].x, x.y+pb[i].y, x.z+pb[i].z, x.w+pb[i].w);
                x.x = (1.f - va.x*va.x) * u.x * (1.f - va.x*u.x);
                x.y = (1.f - va.y*va.y) * u.y * (1.f - va.y*u.y);
                x.z = (1.f - va.z*va.z) * u.z * (1.f - va.z*u.z);
                x.w = (1.f - va.w*va.w) * u.w * (1.f - va.w*u.w);
            }
            float4 h4, l4;
            tf32split(x.x, h4.x, l4.x); tf32split(x.y, h4.y, l4.y);
            tf32split(x.z, h4.z, l4.z); tf32split(x.w, h4.w, l4.w);
            uint32_t off = swz((uint32_t)((i * 32 + ar) * 128 + ac * 16));
            *(float4*)(smem + (buf * BUF_B) + off)          = h4;
            *(float4*)(smem + (buf * BUF_B) + TILE_B + off) = l4;
        }
    };
    auto ldg_B = [&](int ch, int buf) {
        int k0 = kbase + ch * KCH;
        uint32_t b = sb + buf * BUF_B;
        #pragma unroll
        for (int i = 0; i < 4; i++) {
            int id = i * 256 + t;
            int r = id >> 3, cc = id & 7;
            uint32_t so = swz((uint32_t)(r * 128 + cc * 16));
            cp16(b + 2 * TILE_B + so, Bh + (size_t)(nb * 128 + r) * ldb + k0 + cc * 4);
            cp16(b + 3 * TILE_B + so, Bl + (size_t)(nb * 128 + r) * ldb + k0 + cc * 4);
        }
        asm volatile("cp.async.commit_group;" ::: "memory");
    };
    auto compute = [&](int buf) {
        uint32_t b = sb + buf * BUF_B;
        #pragma unroll
        for (int s8 = 0; s8 < 4; s8++) {
            uint32_t ko = (uint32_t)(s8 * 32);
            uint32_t ah[4][4], al[4][4], bh[2][4], bl[2][4];
            #pragma unroll
            for (int i = 0; i < 4; i++) {
                ldsm4(ah[i], b + rowA[i] + ((ko + hA) ^ crA[i]));
                ldsm4(al[i], b + TILE_B + rowA[i] + ((ko + hA) ^ crA[i]));
            }
            #pragma unroll
            for (int jp = 0; jp < 2; jp++) {
                ldsm4(bh[jp], b + 2 * TILE_B + rowB[jp] + ((ko + hB) ^ crB[jp]));
                ldsm4(bl[jp], b + 3 * TILE_B + rowB[jp] + ((ko + hB) ^ crB[jp]));
            }
            #pragma unroll
            for (int i = 0; i < 4; i++)
                #pragma unroll
                for (int j = 0; j < 4; j++)
                    mma8(acc[i][j], ah[i], &bh[j >> 1][(j & 1) * 2]);
            #pragma unroll
            for (int i = 0; i < 4; i++)
                #pragma unroll
                for (int j = 0; j < 4; j++)
                    mma8(acc[i][j], al[i], &bh[j >> 1][(j & 1) * 2]);
            #pragma unroll
            for (int i = 0; i < 4; i++)
                #pragma unroll
                for (int j = 0; j < 4; j++)
                    mma8(acc[i][j], ah[i], &bl[j >> 1][(j & 1) * 2]);
        }
    };

    ldg_A(0); sts_A(0); ldg_B(0, 0);
    ldg_A(1); sts_A(1); ldg_B(1, 1);

    for (int ch = 0; ch < NCH; ch++) {
        int buf = ch & 1;
        if (ch == NCH - 1) asm volatile("cp.async.wait_group 0;" ::: "memory");
        else               asm volatile("cp.async.wait_group 1;" ::: "memory");
        __syncthreads();
        bool pre = (ch + 2 < NCH);
        if (pre) ldg_A(ch + 2);
        compute(buf);
        __syncthreads();
        if (pre) { sts_A(buf); ldg_B(ch + 2, buf); }
    }

    float* Cz = Cbase + (size_t)z * zstride;
    #pragma unroll
    for (int i = 0; i < 4; i++) {
        int row = mb * 128 + m0w + i * 16 + (lane >> 2);
        #pragma unroll
        for (int j = 0; j < 4; j++) {
            int col = nb * 128 + n0w + j * 8 + (lane & 3) * 2;
            float* p = Cz + (size_t)row * ldc + col;
            *(float2*)p              = make_float2(acc[i][j][0], acc[i][j][1]);
            *(float2*)(p + 8 * ldc)  = make_float2(acc[i][j][2], acc[i][j][3]);
        }
    }
}

// ---------------- weight transpose + tf32 split (+ full fp32 transpose) ----------------
__global__ void __launch_bounds__(256) prep_w1(const float* __restrict__ W1) {
    int o = blockIdx.x * 256 + threadIdx.x;
    int n = o >> 9, k = o & 511;
    float v = W1[(size_t)k * HID + n];
    g_W1T[o] = v;
    tf32split(v, g_W1Th[o], g_W1Tl[o]);
}
__global__ void __launch_bounds__(256) prep_w2(const float* __restrict__ W2) {
    int o = blockIdx.x * 256 + threadIdx.x;
    int d = o >> 11, h = o & 2047;
    float v = W2[(size_t)h * DIM + d];
    g_W2T[o] = v;
    tf32split(v, g_W2Th[o], g_W2Tl[o]);
}

// ---------------- a = tanh((y + c*kprev) @ W1 + b1), warp-per-output ----------------
__global__ void __launch_bounds__(256) hcalc2_kernel(
    const float* __restrict__ y, const float* __restrict__ kprev,
    const float* __restrict__ ts, int interval, float cmul,
    const float* __restrict__ b1, float* __restrict__ aout)
{
    __shared__ float ysh[DIM];
    int t = threadIdx.x, lane = t & 31, wid = t >> 5;
    float dt = (ts[interval+1] - ts[interval]) * (1.0f / SUBSTEPS);
    float c = cmul * dt;
    ysh[t]       = y[t]       + c * kprev[t];
    ysh[t + 256] = y[t + 256] + c * kprev[t + 256];
    __syncthreads();
    int j = blockIdx.x * 8 + wid;
    const float4* w4 = (const float4*)(g_W1T + (size_t)j * DIM);
    const float4* y4 = (const float4*)ysh;
    float acc = 0.f;
    #pragma unroll
    for (int i = 0; i < 4; i++) {
        float4 wv = w4[lane + i * 32];
        float4 yv = y4[lane + i * 32];
        acc += wv.x*yv.x + wv.y*yv.y + wv.z*yv.z + wv.w*yv.w;
    }
    #pragma unroll
    for (int o = 16; o > 0; o >>= 1) acc += __shfl_xor_sync(0xffffffffu, acc, o);
    if (lane == 0) aout[j] = tanhf(acc + b1[j]);
}

// ---------------- dy = a @ W2 + b2, warp-per-output ----------------
__global__ void __launch_bounds__(256) dycalc2_kernel(
    const float* __restrict__ avec, const float* __restrict__ b2,
    float* __restrict__ dyout)
{
    __shared__ float ash[HID];
    int t = threadIdx.x, lane = t & 31, wid = t >> 5;
    #pragma unroll
    for (int i = 0; i < 2; i++)
        *(float4*)&ash[(t + i * 256) * 4] = *(const float4*)&avec[(t + i * 256) * 4];
    __syncthreads();
    int d = blockIdx.x * 8 + wid;
    const float4* w4 = (const float4*)(g_W2T + (size_t)d * HID);
    const float4* a4 = (const float4*)ash;
    float acc = 0.f;
    #pragma unroll
    for (int i = 0; i < 16; i++) {
        float4 wv = w4[lane + i * 32];
        float4 av = a4[lane + i * 32];
        acc += wv.x*av.x + wv.y*av.y + wv.z*av.z + wv.w*av.w;
    }
    #pragma unroll
    for (int o = 16; o > 0; o >>= 1) acc += __shfl_xor_sync(0xffffffffu, acc, o);
    if (lane == 0) dyout[d] = acc + b2[d];
}

// ---------------- reduce the 8 GEMM-C split-K partials -> kDy[stage] (s=0..2) ----------------
__global__ void __launch_bounds__(256) reduce_kernel(float* __restrict__ dst)
{
    int i = blockIdx.x * 256 + threadIdx.x;
    float s = 0.f;
    #pragma unroll
    for (int zz = 0; zz < 8; zz++) s += g_kDyP[(size_t)zz * ND + i];
    dst[i] = s;
}

// ---------------- RK4 combine; k4 read directly from the 8 partials ----------------
__global__ void __launch_bounds__(256) combine_kernel(const float* __restrict__ ts, int interval)
{
    int i = blockIdx.x * 256 + threadIdx.x;
    float dt = (ts[interval+1] - ts[interval]) * (1.0f / SUBSTEPS);
    float w = dt * (1.0f / 6.0f);
    if (i < ND) {
        float k4 = 0.f;
        #pragma unroll
        for (int zz = 0; zz < 8; zz++) k4 += g_kDyP[(size_t)zz * ND + i];
        float s = (g_kDy[i] + k4)
                + 2.f * (g_kDy[(size_t)ND + i] + g_kDy[2*(size_t)ND + i]);
        g_Dy[i] += w * s;
    } else if (i < ND + DIM) {
        int d = i - ND;
        g_y[d] += w * (g_kdy[d] + 2.f*g_kdy[DIM + d] + 2.f*g_kdy[2*DIM + d] + g_kdy[3*DIM + d]);
    }
}

// ---------------- driver: forked-stream capture, per-stage a[] slots ----------------
extern "C" void kernel_launch(void* const* d_in, const int* in_sizes, int n_in,
                              void* d_out, int out_size)
{
    (void)in_sizes; (void)n_in; (void)out_size;
    const float* ts  = (const float*)d_in[0];
    const float* y0  = (const float*)d_in[1];
    const float* Dy0 = (const float*)d_in[2];
    const float* W1  = (const float*)d_in[3];
    const float* b1  = (const float*)d_in[4];
    const float* W2  = (const float*)d_in[5];
    const float* b2  = (const float*)d_in[6];
    float* out = (float*)d_out;

    // streams/events created ONCE on the (uncaptured) correctness call; no device mem.
    static cudaStream_t sB = nullptr;
    static cudaEvent_t evFork = nullptr, evA = nullptr, evDy = nullptr;
    if (!sB) {
        cudaStreamCreateWithFlags(&sB, cudaStreamNonBlocking);
        cudaEventCreateWithFlags(&evFork, cudaEventDisableTiming);
        cudaEventCreateWithFlags(&evA,    cudaEventDisableTiming);
        cudaEventCreateWithFlags(&evDy,   cudaEventDisableTiming);
    }

    float *y, *Dy, *a, *kdy, *kDy, *kDyP, *G;
    float *W1Th, *W1Tl, *W2Th, *W2Tl;
    cudaGetSymbolAddress((void**)&y,    g_y);
    cudaGetSymbolAddress((void**)&Dy,   g_Dy);
    cudaGetSymbolAddress((void**)&a,    g_a);
    cudaGetSymbolAddress((void**)&kdy,  g_kdy);
    cudaGetSymbolAddress((void**)&kDy,  g_kDy);
    cudaGetSymbolAddress((void**)&kDyP, g_kDyP);
    cudaGetSymbolAddress((void**)&G,    g_G);
    cudaGetSymbolAddress((void**)&W1Th, g_W1Th);
    cudaGetSymbolAddress((void**)&W1Tl, g_W1Tl);
    cudaGetSymbolAddress((void**)&W2Th, g_W2Th);
    cudaGetSymbolAddress((void**)&W2Tl, g_W2Tl);

    cudaFuncSetAttribute(gemm_mma<1>, cudaFuncAttributeMaxDynamicSharedMemorySize, GEMM_SMEM);
    cudaFuncSetAttribute(gemm_mma<2>, cudaFuncAttributeMaxDynamicSharedMemorySize, GEMM_SMEM);

    // init state + t=0 output slice (origin stream)
    cudaMemcpyAsync(y,  y0,  DIM*sizeof(float), cudaMemcpyDeviceToDevice, 0);
    cudaMemcpyAsync(Dy, Dy0, (size_t)ND*sizeof(float), cudaMemcpyDeviceToDevice, 0);
    cudaMemcpyAsync(out, y0, DIM*sizeof(float), cudaMemcpyDeviceToDevice, 0);
    cudaMemcpyAsync(out + DIM, Dy0, (size_t)ND*sizeof(float), cudaMemcpyDeviceToDevice, 0);
    prep_w1<<<(HID*DIM)/256, 256>>>(W1);
    prep_w2<<<(DIM*HID)/256, 256>>>(W2);

    const float CM[4] = {0.f, 0.5f, 0.5f, 1.f};
    const size_t GSTR = (size_t)NBR * HID;
    for (int interval = 0; interval < NSTEPS; interval++) {
        for (int sub = 0; sub < SUBSTEPS; sub++) {
            // fork: small chain (hcalc->dycalc) on sB, big chain (gemms) on origin
            cudaEventRecord(evFork, 0);
            cudaStreamWaitEvent(sB, evFork, 0);
            for (int s = 0; s < 4; s++) {
                const float* kprev = s ? (kdy + (size_t)(s-1)*DIM) : y;
                float* as = a + (size_t)s * HID;   // per-stage slot: no reuse inside substep
                hcalc2_kernel<<<256, 256, 0, sB>>>(y, kprev, ts, interval, CM[s], b1, as);
                cudaEventRecord(evA, sB);                 // 'a' ready for gemm-C
                dycalc2_kernel<<<64, 256, 0, sB>>>(as, b2, kdy + (size_t)s*DIM);
                gemm_mma<1><<<dim3(16,4,2), 256, GEMM_SMEM>>>(
                    Dy, s ? (kDy + (size_t)(s-1)*ND) : nullptr, DIM,
                    ts, interval, CM[s], nullptr,
                    W1Th, W1Tl, DIM, G, HID, GSTR);
                cudaStreamWaitEvent(0, evA, 0);
                gemm_mma<2><<<dim3(4,4,8), 256, GEMM_SMEM>>>(
                    G, G + GSTR, HID,
                    ts, interval, 0.f, as,
                    W2Th, W2Tl, HID, kDyP, DIM, (size_t)ND);
                if (s < 3)
                    reduce_kernel<<<ND/256, 256>>>(kDy + (size_t)s*ND);
            }
            cudaEventRecord(evDy, sB);                    // join before combine
            cudaStreamWaitEvent(0, evDy, 0);
            combine_kernel<<<(ND + DIM + 255)/256, 256>>>(ts, interval);
        }
        float* dst = out + (size_t)(interval+1) * (1 + NBR) * DIM;
        cudaMemcpyAsync(dst, y, DIM*sizeof(float), cudaMemcpyDeviceToDevice, 0);
        cudaMemcpyAsync(dst + DIM, Dy, (size_t)ND*sizeof(float), cudaMemcpyDeviceToDevice, 0);
    }
}

// round 13
// speedup vs baseline: 1.0092x; 1.0092x over previous
#include <cuda_runtime.h>
#include <cstddef>
#include <cstdint>

#define DIM 512
#define HID 2048
#define NBR 512
#define ND (NBR*DIM)
#define NSTEPS 8
#define SUBSTEPS 2

// ---------------- device scratch (static allocation, allowed) ----------------
__device__ float g_y[DIM];
__device__ float g_Dy[ND];
__device__ float g_a[4*HID];                  // one slot per RK4 stage (WAR-free)
__device__ float g_kdy[4*DIM];
__device__ float g_kDy[4*ND];                 // reduced kDy per stage (s=3 unused)
__device__ float g_kDyP[8*ND];                // GEMM-C split-K partials (z=8)
__device__ float g_G[2*(size_t)NBR*HID];      // GEMM-G split-K partials (z=2), raw
__device__ float g_W1Th[(size_t)HID*DIM], g_W1Tl[(size_t)HID*DIM];  // W1^T split [2048x512]
__device__ float g_W2Th[(size_t)DIM*HID], g_W2Tl[(size_t)DIM*HID];  // W2^T split [512x2048]
__device__ float g_W1T[(size_t)HID*DIM];      // W1^T full fp32 (for matvec)
__device__ float g_W2T[(size_t)DIM*HID];      // W2^T full fp32 (for matvec)

// ---------------- PTX helpers (all sm_80 family-common; NO tcgen05, NO PDL) ----------------
static __device__ __forceinline__ uint32_t s2u(const void* p) {
    uint32_t a;
    asm("{ .reg .u64 t; cvta.to.shared.u64 t, %1; cvt.u32.u64 %0, t; }" : "=r"(a) : "l"(p));
    return a;
}
static __device__ __forceinline__ void cp16(uint32_t s, const void* g) {
    asm volatile("cp.async.cg.shared.global [%0], [%1], 16;" :: "r"(s), "l"(g));
}
static __device__ __forceinline__ uint32_t swz(uint32_t o) { return o ^ ((o >> 3) & 0x70); }

static __device__ __forceinline__ void ldsm4(uint32_t* r, uint32_t addr) {
    asm volatile("ldmatrix.sync.aligned.m8n8.x4.shared.b16 {%0,%1,%2,%3}, [%4];"
                 : "=r"(r[0]), "=r"(r[1]), "=r"(r[2]), "=r"(r[3]) : "r"(addr));
}
static __device__ __forceinline__ void mma8(float* c, const uint32_t* a, const uint32_t* b) {
    asm volatile("mma.sync.aligned.m16n8k8.row.col.f32.tf32.tf32.f32 "
                 "{%0,%1,%2,%3}, {%4,%5,%6,%7}, {%8,%9}, {%0,%1,%2,%3};"
                 : "+f"(c[0]), "+f"(c[1]), "+f"(c[2]), "+f"(c[3])
                 : "r"(a[0]), "r"(a[1]), "r"(a[2]), "r"(a[3]), "r"(b[0]), "r"(b[1]));
}

// tf32 hi/lo split: x ≈ h + l, both tf32-representable; product error ~2^-21
static __device__ __forceinline__ void tf32split(float x, float& h, float& l) {
    uint32_t hb; asm("cvt.rna.tf32.f32 %0, %1;" : "=r"(hb) : "f"(x));
    float hf = __uint_as_float(hb);
    float r = x - hf;
    uint32_t lb; asm("cvt.rna.tf32.f32 %0, %1;" : "=r"(lb) : "f"(r));
    h = hf; l = __uint_as_float(lb);
}

// ---------------- mma.sync tf32 GEMM with FUSED A-prep, 3-pass split ----------------
// AMODE 1: x = A + c*A2 (A2 may be null)            [GEMM-G: RK4 stage axpy]
// AMODE 2: u = A + A2; x = s*u*(1-a*u), a=avec[k]   [GEMM-C: G-sum + tanh-Jacobian epi]
#define KCH 32
#define NCH 8
#define KSUB 256
#define TILE_B (128*KCH*4)
#define BUF_B (4*TILE_B)
#define GEMM_SMEM (2*BUF_B)

template<int AMODE>
__global__ void __launch_bounds__(256, 1)
gemm_mma(const float* __restrict__ A, const float* __restrict__ A2, int lda,
         const float* __restrict__ ts, int interval, float cmul,
         const float* __restrict__ avec,
         const float* __restrict__ Bh, const float* __restrict__ Bl, int ldb,
         float* __restrict__ Cbase, int ldc, size_t zstride)
{
    extern __shared__ __align__(1024) char smem[];
    const uint32_t sb = s2u(smem);
    const int t = threadIdx.x, lane = t & 31, wid = t >> 5;
    const int nb = blockIdx.x, mb = blockIdx.y, z = blockIdx.z;
    const int kbase = z * KSUB;
    const int m0w = (wid & 1) * 64, n0w = (wid >> 1) * 32;

    float c = 0.f;
    if (AMODE == 1)
        c = cmul * (ts[interval+1] - ts[interval]) * (1.0f / SUBSTEPS);

    const int rAl = (lane & 7) + ((lane >> 3) & 1) * 8;
    const int hA  = (lane >> 4) * 16;
    const int rBl = (lane & 7) + ((lane >> 4) & 1) * 8;
    const int hB  = ((lane >> 3) & 1) * 16;
    uint32_t rowA[4], crA[4], rowB[2], crB[2];
    #pragma unroll
    for (int i = 0; i < 4; i++) {
        int row = m0w + i * 16 + rAl;
        rowA[i] = (uint32_t)row * 128u; crA[i] = (uint32_t)(row & 7) * 16u;
    }
    #pragma unroll
    for (int jp = 0; jp < 2; jp++) {
        int row = n0w + jp * 16 + rBl;
        rowB[jp] = (uint32_t)row * 128u; crB[jp] = (uint32_t)(row & 7) * 16u;
    }

    float acc[4][4][4];
    #pragma unroll
    for (int i = 0; i < 4; i++)
        #pragma unroll
        for (int j = 0; j < 4; j++)
            #pragma unroll
            for (int q = 0; q < 4; q++) acc[i][j][q] = 0.f;

    const int ar = t >> 3, ac = t & 7;
    float4 pa[4], pb[4], va;

    auto ldg_A = [&](int ch) {
        int k0 = kbase + ch * KCH + ac * 4;
        #pragma unroll
        for (int i = 0; i < 4; i++) {
            size_t off = (size_t)(mb * 128 + i * 32 + ar) * lda + k0;
            pa[i] = *(const float4*)(A + off);
            if (AMODE == 2)        pb[i] = *(const float4*)(A2 + off);
            else if (A2)           pb[i] = *(const float4*)(A2 + off);
        }
        if (AMODE == 2) va = *(const float4*)(avec + k0);
    };
    auto sts_A = [&](int buf) {
        #pragma unroll
        for (int i = 0; i < 4; i++) {
            float4 x = pa[i];
            if (AMODE == 1) {
                if (A2) { x.x += c*pb[i].x; x.y += c*pb[i].y; x.z += c*pb[i].z; x.w += c*pb[i].w; }
            } else {
                float4 u = make_float4(x.x+pb[i].x, x.y+pb[i].y, x.z+pb[i].z, x.w+pb[i].w);
                x.x = (1.f - va.x*va.x) * u.x * (1.f - va.x*u.x);
                x.y = (1.f - va.y*va.y) * u.y * (1.f - va.y*u.y);
                x.z = (1.f - va.z*va.z) * u.z * (1.f - va.z*u.z);
                x.w = (1.f - va.w*va.w) * u.w * (1.f - va.w*u.w);
            }
            float4 h4, l4;
            tf32split(x.x, h4.x, l4.x); tf32split(x.y, h4.y, l4.y);
            tf32split(x.z, h4.z, l4.z); tf32split(x.w, h4.w, l4.w);
            uint32_t off = swz((uint32_t)((i * 32 + ar) * 128 + ac * 16));
            *(float4*)(smem + (buf * BUF_B) + off)          = h4;
            *(float4*)(smem + (buf * BUF_B) + TILE_B + off) = l4;
        }
    };
    auto ldg_B = [&](int ch, int buf) {
        int k0 = kbase + ch * KCH;
        uint32_t b = sb + buf * BUF_B;
        #pragma unroll
        for (int i = 0; i < 4; i++) {
            int id = i * 256 + t;
            int r = id >> 3, cc = id & 7;
            uint32_t so = swz((uint32_t)(r * 128 + cc * 16));
            cp16(b + 2 * TILE_B + so, Bh + (size_t)(nb * 128 + r) * ldb + k0 + cc * 4);
            cp16(b + 3 * TILE_B + so, Bl + (size_t)(nb * 128 + r) * ldb + k0 + cc * 4);
        }
        asm volatile("cp.async.commit_group;" ::: "memory");
    };
    auto compute = [&](int buf) {
        uint32_t b = sb + buf * BUF_B;
        #pragma unroll
        for (int s8 = 0; s8 < 4; s8++) {
            uint32_t ko = (uint32_t)(s8 * 32);
            uint32_t ah[4][4], al[4][4], bh[2][4], bl[2][4];
            #pragma unroll
            for (int i = 0; i < 4; i++) {
                ldsm4(ah[i], b + rowA[i] + ((ko + hA) ^ crA[i]));
                ldsm4(al[i], b + TILE_B + rowA[i] + ((ko + hA) ^ crA[i]));
            }
            #pragma unroll
            for (int jp = 0; jp < 2; jp++) {
                ldsm4(bh[jp], b + 2 * TILE_B + rowB[jp] + ((ko + hB) ^ crB[jp]));
                ldsm4(bl[jp], b + 3 * TILE_B + rowB[jp] + ((ko + hB) ^ crB[jp]));
            }
            #pragma unroll
            for (int i = 0; i < 4; i++)
                #pragma unroll
                for (int j = 0; j < 4; j++)
                    mma8(acc[i][j], ah[i], &bh[j >> 1][(j & 1) * 2]);
            #pragma unroll
            for (int i = 0; i < 4; i++)
                #pragma unroll
                for (int j = 0; j < 4; j++)
                    mma8(acc[i][j], al[i], &bh[j >> 1][(j & 1) * 2]);
            #pragma unroll
            for (int i = 0; i < 4; i++)
                #pragma unroll
                for (int j = 0; j < 4; j++)
                    mma8(acc[i][j], ah[i], &bl[j >> 1][(j & 1) * 2]);
        }
    };

    ldg_A(0); sts_A(0); ldg_B(0, 0);
    ldg_A(1); sts_A(1); ldg_B(1, 1);

    for (int ch = 0; ch < NCH; ch++) {
        int buf = ch & 1;
        if (ch == NCH - 1) asm volatile("cp.async.wait_group 0;" ::: "memory");
        else               asm volatile("cp.async.wait_group 1;" ::: "memory");
        __syncthreads();
        bool pre = (ch + 2 < NCH);
        if (pre) ldg_A(ch + 2);
        compute(buf);
        __syncthreads();
        if (pre) { sts_A(buf); ldg_B(ch + 2, buf); }
    }

    float* Cz = Cbase + (size_t)z * zstride;
    #pragma unroll
    for (int i = 0; i < 4; i++) {
        int row = mb * 128 + m0w + i * 16 + (lane >> 2);
        #pragma unroll
        for (int j = 0; j < 4; j++) {
            int col = nb * 128 + n0w + j * 8 + (lane & 3) * 2;
            float* p = Cz + (size_t)row * ldc + col;
            *(float2*)p              = make_float2(acc[i][j][0], acc[i][j][1]);
            *(float2*)(p + 8 * ldc)  = make_float2(acc[i][j][2], acc[i][j][3]);
        }
    }
}

// ---------------- weight transpose + tf32 split (+ full fp32 transpose) ----------------
__global__ void __launch_bounds__(256) prep_w1(const float* __restrict__ W1) {
    int o = blockIdx.x * 256 + threadIdx.x;
    int n = o >> 9, k = o & 511;
    float v = W1[(size_t)k * HID + n];
    g_W1T[o] = v;
    tf32split(v, g_W1Th[o], g_W1Tl[o]);
}
__global__ void __launch_bounds__(256) prep_w2(const float* __restrict__ W2) {
    int o = blockIdx.x * 256 + threadIdx.x;
    int d = o >> 11, h = o & 2047;
    float v = W2[(size_t)h * DIM + d];
    g_W2T[o] = v;
    tf32split(v, g_W2Th[o], g_W2Tl[o]);
}

// ---------------- a = tanh((y + c*kprev) @ W1 + b1), warp-per-output ----------------
__global__ void __launch_bounds__(256) hcalc2_kernel(
    const float* __restrict__ y, const float* __restrict__ kprev,
    const float* __restrict__ ts, int interval, float cmul,
    const float* __restrict__ b1, float* __restrict__ aout)
{
    __shared__ float ysh[DIM];
    int t = threadIdx.x, lane = t & 31, wid = t >> 5;
    float dt = (ts[interval+1] - ts[interval]) * (1.0f / SUBSTEPS);
    float c = cmul * dt;
    ysh[t]       = y[t]       + c * kprev[t];
    ysh[t + 256] = y[t + 256] + c * kprev[t + 256];
    __syncthreads();
    int j = blockIdx.x * 8 + wid;
    const float4* w4 = (const float4*)(g_W1T + (size_t)j * DIM);
    const float4* y4 = (const float4*)ysh;
    float acc = 0.f;
    #pragma unroll
    for (int i = 0; i < 4; i++) {
        float4 wv = w4[lane + i * 32];
        float4 yv = y4[lane + i * 32];
        acc += wv.x*yv.x + wv.y*yv.y + wv.z*yv.z + wv.w*yv.w;
    }
    #pragma unroll
    for (int o = 16; o > 0; o >>= 1) acc += __shfl_xor_sync(0xffffffffu, acc, o);
    if (lane == 0) aout[j] = tanhf(acc + b1[j]);
}

// ---------------- dy = a @ W2 + b2, warp-per-output ----------------
__global__ void __launch_bounds__(256) dycalc2_kernel(
    const float* __restrict__ avec, const float* __restrict__ b2,
    float* __restrict__ dyout)
{
    __shared__ float ash[HID];
    int t = threadIdx.x, lane = t & 31, wid = t >> 5;
    #pragma unroll
    for (int i = 0; i < 2; i++)
        *(float4*)&ash[(t + i * 256) * 4] = *(const float4*)&avec[(t + i * 256) * 4];
    __syncthreads();
    int d = blockIdx.x * 8 + wid;
    const float4* w4 = (const float4*)(g_W2T + (size_t)d * HID);
    const float4* a4 = (const float4*)ash;
    float acc = 0.f;
    #pragma unroll
    for (int i = 0; i < 16; i++) {
        float4 wv = w4[lane + i * 32];
        float4 av = a4[lane + i * 32];
        acc += wv.x*av.x + wv.y*av.y + wv.z*av.z + wv.w*av.w;
    }
    #pragma unroll
    for (int o = 16; o > 0; o >>= 1) acc += __shfl_xor_sync(0xffffffffu, acc, o);
    if (lane == 0) dyout[d] = acc + b2[d];
}

// ---------------- reduce the 8 GEMM-C split-K partials -> kDy[stage] (s=0..2) ----------------
__global__ void __launch_bounds__(256) reduce_kernel(float* __restrict__ dst)
{
    int i = blockIdx.x * 256 + threadIdx.x;
    float s = 0.f;
    #pragma unroll
    for (int zz = 0; zz < 8; zz++) s += g_kDyP[(size_t)zz * ND + i];
    dst[i] = s;
}

// ---------------- RK4 combine; k4 read directly from the 8 partials ----------------
__global__ void __launch_bounds__(256) combine_kernel(const float* __restrict__ ts, int interval)
{
    int i = blockIdx.x * 256 + threadIdx.x;
    float dt = (ts[interval+1] - ts[interval]) * (1.0f / SUBSTEPS);
    float w = dt * (1.0f / 6.0f);
    if (i < ND) {
        float k4 = 0.f;
        #pragma unroll
        for (int zz = 0; zz < 8; zz++) k4 += g_kDyP[(size_t)zz * ND + i];
        float s = (g_kDy[i] + k4)
                + 2.f * (g_kDy[(size_t)ND + i] + g_kDy[2*(size_t)ND + i]);
        g_Dy[i] += w * s;
    } else if (i < ND + DIM) {
        int d = i - ND;
        g_y[d] += w * (g_kdy[d] + 2.f*g_kdy[DIM + d] + 2.f*g_kdy[2*DIM + d] + g_kdy[3*DIM + d]);
    }
}

// ---------------- driver: forked streams; output copies off the critical path ----------------
extern "C" void kernel_launch(void* const* d_in, const int* in_sizes, int n_in,
                              void* d_out, int out_size)
{
    (void)in_sizes; (void)n_in; (void)out_size;
    const float* ts  = (const float*)d_in[0];
    const float* y0  = (const float*)d_in[1];
    const float* Dy0 = (const float*)d_in[2];
    const float* W1  = (const float*)d_in[3];
    const float* b1  = (const float*)d_in[4];
    const float* W2  = (const float*)d_in[5];
    const float* b2  = (const float*)d_in[6];
    float* out = (float*)d_out;

    // streams/events created ONCE on the (uncaptured) correctness call; no device mem.
    static cudaStream_t sB = nullptr;
    static cudaEvent_t evFork = nullptr, evA = nullptr, evDy = nullptr;
    if (!sB) {
        cudaStreamCreateWithFlags(&sB, cudaStreamNonBlocking);
        cudaEventCreateWithFlags(&evFork, cudaEventDisableTiming);
        cudaEventCreateWithFlags(&evA,    cudaEventDisableTiming);
        cudaEventCreateWithFlags(&evDy,   cudaEventDisableTiming);
    }

    float *y, *Dy, *a, *kdy, *kDy, *kDyP, *G;
    float *W1Th, *W1Tl, *W2Th, *W2Tl;
    cudaGetSymbolAddress((void**)&y,    g_y);
    cudaGetSymbolAddress((void**)&Dy,   g_Dy);
    cudaGetSymbolAddress((void**)&a,    g_a);
    cudaGetSymbolAddress((void**)&kdy,  g_kdy);
    cudaGetSymbolAddress((void**)&kDy,  g_kDy);
    cudaGetSymbolAddress((void**)&kDyP, g_kDyP);
    cudaGetSymbolAddress((void**)&G,    g_G);
    cudaGetSymbolAddress((void**)&W1Th, g_W1Th);
    cudaGetSymbolAddress((void**)&W1Tl, g_W1Tl);
    cudaGetSymbolAddress((void**)&W2Th, g_W2Th);
    cudaGetSymbolAddress((void**)&W2Tl, g_W2Tl);

    cudaFuncSetAttribute(gemm_mma<1>, cudaFuncAttributeMaxDynamicSharedMemorySize, GEMM_SMEM);
    cudaFuncSetAttribute(gemm_mma<2>, cudaFuncAttributeMaxDynamicSharedMemorySize, GEMM_SMEM);

    // init state + t=0 output slice (origin stream)
    cudaMemcpyAsync(y,  y0,  DIM*sizeof(float), cudaMemcpyDeviceToDevice, 0);
    cudaMemcpyAsync(Dy, Dy0, (size_t)ND*sizeof(float), cudaMemcpyDeviceToDevice, 0);
    cudaMemcpyAsync(out, y0, DIM*sizeof(float), cudaMemcpyDeviceToDevice, 0);
    cudaMemcpyAsync(out + DIM, Dy0, (size_t)ND*sizeof(float), cudaMemcpyDeviceToDevice, 0);
    prep_w1<<<(HID*DIM)/256, 256>>>(W1);
    prep_w2<<<(DIM*HID)/256, 256>>>(W2);

    const float CM[4] = {0.f, 0.5f, 0.5f, 1.f};
    const size_t GSTR = (size_t)NBR * HID;
    const size_t OSTR = (size_t)(1 + NBR) * DIM;
    for (int interval = 0; interval < NSTEPS; interval++) {
        for (int sub = 0; sub < SUBSTEPS; sub++) {
            // fork: small chain + output copies on sB, gemm chain on origin
            cudaEventRecord(evFork, 0);
            cudaStreamWaitEvent(sB, evFork, 0);
            if (sub == 0 && interval > 0) {
                // state after interval-1 == output slice 'interval'; copy off critical path.
                // RAW: evFork orders after previous combine. WAR vs this substep's combine:
                // copies precede evDy in sB order; combine waits evDy.
                float* dst = out + (size_t)interval * OSTR;
                cudaMemcpyAsync(dst, y, DIM*sizeof(float), cudaMemcpyDeviceToDevice, sB);
                cudaMemcpyAsync(dst + DIM, Dy, (size_t)ND*sizeof(float),
                                cudaMemcpyDeviceToDevice, sB);
            }
            for (int s = 0; s < 4; s++) {
                const float* kprev = s ? (kdy + (size_t)(s-1)*DIM) : y;
                float* as = a + (size_t)s * HID;   // per-stage slot: no reuse inside substep
                hcalc2_kernel<<<256, 256, 0, sB>>>(y, kprev, ts, interval, CM[s], b1, as);
                cudaEventRecord(evA, sB);                 // 'a' ready for gemm-C
                dycalc2_kernel<<<64, 256, 0, sB>>>(as, b2, kdy + (size_t)s*DIM);
                gemm_mma<1><<<dim3(16,4,2), 256, GEMM_SMEM>>>(
                    Dy, s ? (kDy + (size_t)(s-1)*ND) : nullptr, DIM,
                    ts, interval, CM[s], nullptr,
                    W1Th, W1Tl, DIM, G, HID, GSTR);
                cudaStreamWaitEvent(0, evA, 0);
                gemm_mma<2><<<dim3(4,4,8), 256, GEMM_SMEM>>>(
                    G, G + GSTR, HID,
                    ts, interval, 0.f, as,
                    W2Th, W2Tl, HID, kDyP, DIM, (size_t)ND);
                if (s < 3)
                    reduce_kernel<<<ND/256, 256>>>(kDy + (size_t)s*ND);
            }
            cudaEventRecord(evDy, sB);                    // join before combine
            cudaStreamWaitEvent(0, evDy, 0);
            combine_kernel<<<(ND + DIM + 255)/256, 256>>>(ts, interval);
        }
    }
    // final output slice (state after last interval), origin stream
    float* dst = out + (size_t)NSTEPS * OSTR;
    cudaMemcpyAsync(dst, y, DIM*sizeof(float), cudaMemcpyDeviceToDevice, 0);
    cudaMemcpyAsync(dst + DIM, Dy, (size_t)ND*sizeof(float), cudaMemcpyDeviceToDevice, 0);
}